// round 1
// baseline (speedup 1.0000x reference)
#include <cuda_runtime.h>
#include <math.h>

// Precomputed cos(q_weights[i]) — written by a 1-warp prelude kernel so the
// main kernel doesn't pay 4 MUFU.COS per thread (8M MUFU ops would throttle).
__device__ float g_cosw[4];

__global__ void precompute_cos_kernel(const float* __restrict__ qw) {
    int i = threadIdx.x;
    if (i < 4) g_cosw[i] = cosf(qw[i]);
}

// out[b][i] = cos(theta_i) * (sum_k sign_i(k) * x_k^2) / (sum_k x_k^2)
// sign_i(k) = +1 if bit (3-i) of k is 0, else -1  (wire 0 = MSB)
// Equivalent: out_i = c_i * (2*P_i/T - 1) where P_i = sum over k with bit==0.
__global__ void __launch_bounds__(256) quantum_z_kernel(
    const float4* __restrict__ x, float4* __restrict__ out, int B)
{
    int b = blockIdx.x * blockDim.x + threadIdx.x;
    if (b >= B) return;

    const float4* p = x + (size_t)b * 4;
    float4 v0 = p[0];
    float4 v1 = p[1];
    float4 v2 = p[2];
    float4 v3 = p[3];

    float e[16];
    e[0]=v0.x; e[1]=v0.y; e[2]=v0.z; e[3]=v0.w;
    e[4]=v1.x; e[5]=v1.y; e[6]=v1.z; e[7]=v1.w;
    e[8]=v2.x; e[9]=v2.y; e[10]=v2.z; e[11]=v2.w;
    e[12]=v3.x; e[13]=v3.y; e[14]=v3.z; e[15]=v3.w;

    float sq[16];
    #pragma unroll
    for (int k = 0; k < 16; ++k) {
        float xv = e[k];
        xv = (xv != xv) ? 0.0f : xv;   // NaN scrub (matches reference)
        sq[k] = xv * xv;
    }

    // Total norm^2
    float T = 0.0f;
    #pragma unroll
    for (int k = 0; k < 16; ++k) T += sq[k];

    // P_i = sum of sq[k] where bit (3-i) of k is zero
    float P0 = sq[0]+sq[1]+sq[2]+sq[3]+sq[4]+sq[5]+sq[6]+sq[7];          // bit3==0
    float P1 = sq[0]+sq[1]+sq[2]+sq[3]+sq[8]+sq[9]+sq[10]+sq[11];        // bit2==0
    float P2 = sq[0]+sq[1]+sq[4]+sq[5]+sq[8]+sq[9]+sq[12]+sq[13];        // bit1==0
    float P3 = sq[0]+sq[2]+sq[4]+sq[6]+sq[8]+sq[10]+sq[12]+sq[14];       // bit0==0

    float invT = 1.0f / T;

    float4 r;
    r.x = g_cosw[0] * fmaf(2.0f * P0, invT, -1.0f);
    r.y = g_cosw[1] * fmaf(2.0f * P1, invT, -1.0f);
    r.z = g_cosw[2] * fmaf(2.0f * P2, invT, -1.0f);
    r.w = g_cosw[3] * fmaf(2.0f * P3, invT, -1.0f);

    out[b] = r;
}

extern "C" void kernel_launch(void* const* d_in, const int* in_sizes, int n_in,
                              void* d_out, int out_size) {
    const float* x  = (const float*)d_in[0];
    const float* qw = (const float*)d_in[1];
    float* out = (float*)d_out;

    int B = in_sizes[0] / 16;

    precompute_cos_kernel<<<1, 32>>>(qw);

    int threads = 256;
    int blocks = (B + threads - 1) / threads;
    quantum_z_kernel<<<blocks, threads>>>(
        (const float4*)x, (float4*)out, B);
}